// round 3
// baseline (speedup 1.0000x reference)
#include <cuda_runtime.h>

#define Hd   1024
#define Bb   16
#define Ss   512
#define Kk   32
#define Ee   1024
#define NCAT 3072

__device__ float g_full_nodes[Bb*Kk*Hd];
__device__ float g_node_hidden[Bb*Kk*Hd];
__device__ float g_Aj[Bb*Kk*Hd];
__device__ float g_Ai[Bb*Kk*Hd];
__device__ float g_Wcat[Hd*NCAT];
__device__ float g_cls_hidden[Bb*Hd];
__device__ int   g_n[Bb];

__device__ __forceinline__ float tanh_fast(float x) {
    float e = __expf(2.0f * x);
    return 1.0f - __fdividef(2.0f, e + 1.0f);
}

__device__ __forceinline__ unsigned long long ffma2(unsigned long long a,
                                                    unsigned long long b,
                                                    unsigned long long c) {
    unsigned long long d;
    asm("fma.rn.f32x2 %0, %1, %2, %3;" : "=l"(d) : "l"(a), "l"(b), "l"(c));
    return d;
}

union F2U { float4 f; float2 f2[2]; unsigned long long u[2]; };
union UF2 { unsigned long long u; float2 f2; };

__device__ __forceinline__ void block_reduce2(float& a0, float& a1, float* red) {
    #pragma unroll
    for (int o = 16; o > 0; o >>= 1) {
        a0 += __shfl_down_sync(0xffffffffu, a0, o);
        a1 += __shfl_down_sync(0xffffffffu, a1, o);
    }
    int w = threadIdx.x >> 5;
    if ((threadIdx.x & 31) == 0) { red[2*w] = a0; red[2*w+1] = a1; }
    __syncthreads();
    if (threadIdx.x == 0) {
        a0 = red[0]; a1 = red[1];
        for (int w2 = 1; w2 < (int)(blockDim.x >> 5); w2++) {
            a0 += red[2*w2]; a1 += red[2*w2+1];
        }
    }
}

// -------- 1. segment means + g_n --------------------------------------------
__global__ void k_meta(const float* __restrict__ seq, const int* __restrict__ P) {
    int k = blockIdx.x, b = blockIdx.y;
    int n = 0;
    #pragma unroll
    for (int j = 0; j < Kk - 1; j++) n += (P[b*Kk + 1 + j] > 0);
    if (k == 0 && threadIdx.x == 0) g_n[b] = n;
    float* dst = &g_full_nodes[(b*Kk + k)*Hd];
    if (k < n) {
        int end   = P[b*Kk + 1 + k];
        int start = (k == 0) ? 1 : (P[b*Kk + k] + 1);
        float inv = 1.0f / (float)(end - start + 1);
        #pragma unroll
        for (int u = 0; u < Hd/256; u++) {
            int h = threadIdx.x + u*256;
            float s = 0.0f;
            for (int p = start; p <= end; p++)
                s += seq[((long)b*Ss + p)*Hd + h];
            dst[h] = s * inv;
        }
    } else {
        #pragma unroll
        for (int u = 0; u < Hd/256; u++) dst[threadIdx.x + u*256] = 0.0f;
    }
}

// -------- 2. Wcat = [node_dense_W | W0+W2 | W1-W2] --------------------------
__global__ void k_build_wcat(const float* __restrict__ nodeW, const float* __restrict__ eW) {
    int idx = blockIdx.x*256 + threadIdx.x;
    int kk = idx / NCAT;
    int c  = idx - kk*NCAT;
    float v;
    if (c < Hd) {
        v = nodeW[kk*Hd + c];
    } else if (c < 2*Hd) {
        int h = c - Hd;
        v = eW[kk*Hd + h] + eW[(2*Hd + kk)*Hd + h];
    } else {
        int h = c - 2*Hd;
        v = eW[(Hd + kk)*Hd + h] - eW[(2*Hd + kk)*Hd + h];
    }
    g_Wcat[idx] = v;
}

// -------- 3. batched cls GEMVs: naf (m=0) and cls_hidden (m=1) --------------
// grid (Hd/32, 2), 128 threads. Each block: 32 cols, K split 4-way by warp.
__global__ __launch_bounds__(128) void k_cls2(const float* __restrict__ seq,
                                              const float* __restrict__ nafW,
                                              const float* __restrict__ nafb,
                                              const float* __restrict__ clsW,
                                              const float* __restrict__ clsb) {
    __shared__ float xs[4][64][16];    // [ks][kk][b]
    __shared__ float red[4][32][16];
    int m = blockIdx.y;
    const float* W    = m ? clsW : nafW;
    const float* bias = m ? clsb : nafb;
    int tid = threadIdx.x;
    int lane = tid & 31, ks = tid >> 5;
    int colg = blockIdx.x*32 + lane;

    float acc[16];
    #pragma unroll
    for (int b = 0; b < 16; b++) acc[b] = 0.0f;

    for (int t = 0; t < 4; t++) {
        __syncthreads();
        #pragma unroll
        for (int io = 0; io < 32; io++) {
            int flat = io*128 + tid;
            int b    = flat >> 8;
            int rem  = flat & 255;
            int ks2  = rem >> 6;
            int kk   = rem & 63;
            xs[ks2][kk][b] = seq[(long)b*Ss*Hd + ks2*256 + t*64 + kk];
        }
        __syncthreads();
        #pragma unroll 8
        for (int kk = 0; kk < 64; kk++) {
            float w = W[(ks*256 + t*64 + kk)*Hd + colg];
            #pragma unroll
            for (int b2 = 0; b2 < 8; b2++) {
                float2 x2 = *(const float2*)&xs[ks][kk][b2*2];
                acc[2*b2]   = fmaf(x2.x, w, acc[2*b2]);
                acc[2*b2+1] = fmaf(x2.y, w, acc[2*b2+1]);
            }
        }
    }
    #pragma unroll
    for (int b = 0; b < 16; b++) red[ks][lane][b] = acc[b];
    __syncthreads();
    #pragma unroll
    for (int q = 0; q < 4; q++) {
        int o = q*128 + tid;
        int c = o & 31;
        int b = (o >> 5) & 15;
        float v = red[0][c][b] + red[1][c][b] + red[2][c][b] + red[3][c][b];
        int cg = blockIdx.x*32 + c;
        v += bias[cg];
        if (m == 0) g_full_nodes[(b*Kk + g_n[b])*Hd + cg] = v;
        else        g_cls_hidden[b*Hd + cg] = tanh_fast(v);
    }
}

// -------- 4. cls logits ------------------------------------------------------
__global__ void k_cls_out(const float* __restrict__ oW, const float* __restrict__ ob,
                          float* __restrict__ out) {
    __shared__ float red[8];
    int b = blockIdx.x;
    float a0 = 0.f, a1 = 0.f;
    #pragma unroll
    for (int u = 0; u < Hd/128; u++) {
        int h = threadIdx.x + u*128;
        float t = g_cls_hidden[b*Hd + h];
        a0 = fmaf(t, oW[2*h  ], a0);
        a1 = fmaf(t, oW[2*h+1], a1);
    }
    block_reduce2(a0, a1, red);
    if (threadIdx.x == 0) {
        out[b*2]     = a0 + ob[0];
        out[b*2 + 1] = a1 + ob[1];
    }
}

// -------- 5. fused GEMM with f32x2: 512x3072x1024 ---------------------------
// BM=64, BN=64, BK=32, 128 threads (tm 16 x tn 8), micro 4x8.
// Acc pairs along M (FFMA2). B stored duplicated in smem (dup-pair per col),
// XOR-swizzled chunks for conflict-free broadcast LDS.
__global__ __launch_bounds__(128) void k_gemm_fused(const float* __restrict__ node_b,
                                                    const float* __restrict__ edge_b) {
    __shared__ __align__(16) float  As[32][68];    // [k][m], padded
    __shared__ __align__(16) float2 sB[32][64];    // [k][dup-col], swizzled

    int bn = blockIdx.x, bm = blockIdx.y;
    int tid = threadIdx.x;
    int tm = tid >> 3, tn = tid & 7;
    int sw = (tn >> 1) & 3;

    unsigned long long acc2[2][8];
    #pragma unroll
    for (int p = 0; p < 2; p++)
        #pragma unroll
        for (int j = 0; j < 8; j++) acc2[p][j] = 0ull;

    for (int kt = 0; kt < Hd; kt += 32) {
        // fill A (transpose 64x32 -> [k][m])
        #pragma unroll
        for (int i = 0; i < 4; i++) {
            int f4  = tid + i*128;
            int row = f4 >> 3;
            int kq  = (f4 & 7) * 4;
            float4 v = *(const float4*)&g_full_nodes[(bm*64 + row)*Hd + kt + kq];
            As[kq+0][row] = v.x; As[kq+1][row] = v.y;
            As[kq+2][row] = v.z; As[kq+3][row] = v.w;
        }
        // fill B duplicated + swizzled
        #pragma unroll
        for (int i = 0; i < 4; i++) {
            int f4 = tid + i*128;
            int kr = f4 >> 4;
            int cq = (f4 & 15) * 4;
            float4 v = *(const float4*)&g_Wcat[(kt + kr)*NCAT + bn*64 + cq];
            float vv[4] = {v.x, v.y, v.z, v.w};
            #pragma unroll
            for (int d = 0; d < 4; d++) {
                int c = cq + d;
                int g = c >> 3, u = (c & 7) >> 1, half = c & 1;
                int p = u ^ ((g >> 1) & 3);
                sB[kr][g*8 + p*2 + half] = make_float2(vv[d], vv[d]);
            }
        }
        __syncthreads();
        #pragma unroll 8
        for (int k = 0; k < 32; k++) {
            F2U ua; ua.f = *(const float4*)&As[k][tm*4];
            unsigned long long b2[8];
            #pragma unroll
            for (int u = 0; u < 4; u++) {
                F2U ub; ub.f = *(const float4*)&sB[k][tn*8 + ((u ^ sw) * 2)];
                b2[2*u]   = ub.u[0];
                b2[2*u+1] = ub.u[1];
            }
            #pragma unroll
            for (int j = 0; j < 8; j++) {
                acc2[0][j] = ffma2(ua.u[0], b2[j], acc2[0][j]);
                acc2[1][j] = ffma2(ua.u[1], b2[j], acc2[1][j]);
            }
        }
        __syncthreads();
    }

    int region = bn >> 4;
    #pragma unroll
    for (int p = 0; p < 2; p++) {
        #pragma unroll
        for (int j = 0; j < 8; j++) {
            UF2 w; w.u = acc2[p][j];
            int c = bn*64 + tn*8 + j;
            #pragma unroll
            for (int hh = 0; hh < 2; hh++) {
                int r = bm*64 + tm*4 + p*2 + hh;
                float v = hh ? w.f2.y : w.f2.x;
                if (region == 0) {
                    g_node_hidden[r*Hd + c] = tanh_fast(v + node_b[c]);
                } else if (region == 1) {
                    int h = c - Hd;
                    g_Aj[r*Hd + h] = v + edge_b[h];
                } else {
                    int h = c - 2*Hd;
                    g_Ai[r*Hd + h] = v;
                }
            }
        }
    }
}

// -------- 6. node logits -----------------------------------------------------
__global__ void k_node_out(const float* __restrict__ oW, const float* __restrict__ ob,
                           float* __restrict__ out) {
    __shared__ float red[8];
    int r = blockIdx.x;
    float a0 = 0.f, a1 = 0.f;
    #pragma unroll
    for (int u = 0; u < Hd/128; u++) {
        int h = threadIdx.x + u*128;
        float t = g_node_hidden[r*Hd + h];
        a0 = fmaf(t, oW[2*h  ], a0);
        a1 = fmaf(t, oW[2*h+1], a1);
    }
    block_reduce2(a0, a1, red);
    if (threadIdx.x == 0) {
        out[32 + r*2]     = a0 + ob[0];
        out[32 + r*2 + 1] = a1 + ob[1];
    }
}

// -------- 7. edge logits -----------------------------------------------------
__global__ void k_edge(const float* __restrict__ eb, const float* __restrict__ oW,
                       const float* __restrict__ ob, float* __restrict__ out) {
    __shared__ float red[8];
    int e = blockIdx.x, b = blockIdx.y;
    int m = g_n[b] + 1;
    bool valid = e < m*m;
    int i = min(e / m, Kk - 1);
    int j = min(e % m, Kk - 1);
    const float* aj = &g_Aj[(b*Kk + j)*Hd];
    const float* ai = &g_Ai[(b*Kk + i)*Hd];
    float a0 = 0.f, a1 = 0.f;
    #pragma unroll
    for (int u = 0; u < Hd/128; u++) {
        int h = threadIdx.x + u*128;
        float pre = valid ? (aj[h] + ai[h]) : eb[h];
        float t = tanh_fast(pre);
        a0 = fmaf(t, oW[2*h  ], a0);
        a1 = fmaf(t, oW[2*h+1], a1);
    }
    block_reduce2(a0, a1, red);
    if (threadIdx.x == 0) {
        long base = 32 + Bb*Kk*2 + ((long)b*Ee + e)*2;
        out[base]     = a0 + ob[0];
        out[base + 1] = a1 + ob[1];
    }
}

// ---------------------------------------------------------------------------
extern "C" void kernel_launch(void* const* d_in, const int* in_sizes, int n_in,
                              void* d_out, int out_size) {
    const float* seq   = (const float*)d_in[0];
    const int*   P     = (const int*)d_in[1];
    const float* nafW  = (const float*)d_in[2];
    const float* nafb  = (const float*)d_in[3];
    const float* clsW  = (const float*)d_in[4];
    const float* clsb  = (const float*)d_in[5];
    const float* clsoW = (const float*)d_in[6];
    const float* clsob = (const float*)d_in[7];
    const float* ndW   = (const float*)d_in[8];
    const float* ndb   = (const float*)d_in[9];
    const float* noW   = (const float*)d_in[10];
    const float* nob   = (const float*)d_in[11];
    const float* edW   = (const float*)d_in[12];
    const float* edb   = (const float*)d_in[13];
    const float* eoW   = (const float*)d_in[14];
    const float* eob   = (const float*)d_in[15];
    float* out = (float*)d_out;

    k_meta<<<dim3(Kk, Bb), 256>>>(seq, P);
    k_build_wcat<<<(Hd*NCAT)/256, 256>>>(ndW, edW);
    k_cls2<<<dim3(Hd/32, 2), 128>>>(seq, nafW, nafb, clsW, clsb);
    k_cls_out<<<Bb, 128>>>(clsoW, clsob, out);
    k_gemm_fused<<<dim3(NCAT/64, (Bb*Kk)/64), 128>>>(ndb, edb);
    k_node_out<<<Bb*Kk, 128>>>(noW, nob, out);
    k_edge<<<dim3(Ee, Bb), 128>>>(edb, eoW, eob, out);
}

// round 5
// speedup vs baseline: 1.8642x; 1.8642x over previous
#include <cuda_runtime.h>
#include <cuda_bf16.h>
#include <cstdint>

#define Hd   1024
#define Bb   16
#define Ss   512
#define Kk   32
#define Ee   1024
#define NCAT 3072

// ---------------- scratch ----------------------------------------------------
__device__ __nv_bfloat16 g_Xhi[512*Hd];     // full_nodes hi  [512][1024]
__device__ __nv_bfloat16 g_Xlo[512*Hd];     // full_nodes lo
__device__ __nv_bfloat16 g_Whi[NCAT*Hd];    // Wcat^T hi  [3072 n][1024 k]
__device__ __nv_bfloat16 g_Wlo[NCAT*Hd];    // Wcat^T lo
__device__ float g_node_hidden[512*Hd];
__device__ float g_Aj[512*Hd];
__device__ float g_Ai[512*Hd];
__device__ float g_cls_hidden[Bb*Hd];
__device__ int   g_n[Bb];

// ---------------- helpers ----------------------------------------------------
__device__ __forceinline__ float tanh_fast(float x) {
    float e = __expf(2.0f * x);
    return 1.0f - __fdividef(2.0f, e + 1.0f);
}

__device__ __forceinline__ uint32_t smem_u32(const void* p) {
    uint32_t a;
    asm("{ .reg .u64 t; cvta.to.shared.u64 t, %1; cvt.u32.u64 %0, t; }" : "=r"(a) : "l"(p));
    return a;
}

__device__ __forceinline__ void ldsm_x4(uint32_t& r0, uint32_t& r1, uint32_t& r2,
                                        uint32_t& r3, uint32_t addr) {
    asm volatile("ldmatrix.sync.aligned.m8n8.x4.shared.b16 {%0,%1,%2,%3}, [%4];"
                 : "=r"(r0), "=r"(r1), "=r"(r2), "=r"(r3) : "r"(addr));
}
__device__ __forceinline__ void ldsm_x2(uint32_t& r0, uint32_t& r1, uint32_t addr) {
    asm volatile("ldmatrix.sync.aligned.m8n8.x2.shared.b16 {%0,%1}, [%2];"
                 : "=r"(r0), "=r"(r1) : "r"(addr));
}
__device__ __forceinline__ void mma16816(float* d, const uint32_t* a, const uint32_t* b) {
    asm volatile(
        "mma.sync.aligned.m16n8k16.row.col.f32.bf16.bf16.f32 "
        "{%0,%1,%2,%3}, {%4,%5,%6,%7}, {%8,%9}, {%0,%1,%2,%3};"
        : "+f"(d[0]), "+f"(d[1]), "+f"(d[2]), "+f"(d[3])
        : "r"(a[0]), "r"(a[1]), "r"(a[2]), "r"(a[3]), "r"(b[0]), "r"(b[1]));
}

__device__ __forceinline__ void block_reduce2(float& a0, float& a1, float* red) {
    #pragma unroll
    for (int o = 16; o > 0; o >>= 1) {
        a0 += __shfl_down_sync(0xffffffffu, a0, o);
        a1 += __shfl_down_sync(0xffffffffu, a1, o);
    }
    int w = threadIdx.x >> 5;
    if ((threadIdx.x & 31) == 0) { red[2*w] = a0; red[2*w+1] = a1; }
    __syncthreads();
    if (threadIdx.x == 0) {
        a0 = red[0]; a1 = red[1];
        for (int w2 = 1; w2 < (int)(blockDim.x >> 5); w2++) {
            a0 += red[2*w2]; a1 += red[2*w2+1];
        }
    }
}

__device__ __forceinline__ void split_store(__nv_bfloat16* hi, __nv_bfloat16* lo,
                                            long idx, float v) {
    __nv_bfloat16 h = __float2bfloat16(v);
    hi[idx] = h;
    lo[idx] = __float2bfloat16(v - __bfloat162float(h));
}

// -------- 0. segment means -> Xhi/Xlo; g_n ----------------------------------
__global__ void k_meta(const float* __restrict__ seq, const int* __restrict__ P) {
    int k = blockIdx.x, b = blockIdx.y;
    int n = 0;
    #pragma unroll
    for (int j = 0; j < Kk - 1; j++) n += (P[b*Kk + 1 + j] > 0);
    if (k == 0 && threadIdx.x == 0) g_n[b] = n;
    long row = (long)(b*Kk + k) * Hd;
    if (k < n) {
        int end   = P[b*Kk + 1 + k];
        int start = (k == 0) ? 1 : (P[b*Kk + k] + 1);
        float inv = 1.0f / (float)(end - start + 1);
        #pragma unroll
        for (int u = 0; u < Hd/256; u++) {
            int h = threadIdx.x + u*256;
            float s = 0.0f;
            for (int p = start; p <= end; p++)
                s += seq[((long)b*Ss + p)*Hd + h];
            split_store(g_Xhi, g_Xlo, row + h, s * inv);
        }
    } else {
        #pragma unroll
        for (int u = 0; u < Hd/256; u++) {
            int h = threadIdx.x + u*256;
            g_Xhi[row + h] = __float2bfloat16(0.f);
            g_Xlo[row + h] = __float2bfloat16(0.f);
        }
    }
}

// -------- 1. transposed hi/lo weight build: Whi/Wlo[n][k] -------------------
__global__ void k_wsplit(const float* __restrict__ nodeW, const float* __restrict__ eW) {
    __shared__ float tile[32][33];
    int tx = threadIdx.x, ty = threadIdx.y;
    int c0 = blockIdx.x * 32, k0 = blockIdx.y * 32;
    #pragma unroll
    for (int r = 0; r < 4; r++) {
        int kk = k0 + ty + r*8;
        int c  = c0 + tx;
        float v;
        if (c < Hd) {
            v = nodeW[kk*Hd + c];
        } else if (c < 2*Hd) {
            int h = c - Hd;
            v = eW[kk*Hd + h] + eW[(2*Hd + kk)*Hd + h];
        } else {
            int h = c - 2*Hd;
            v = eW[(Hd + kk)*Hd + h] - eW[(2*Hd + kk)*Hd + h];
        }
        tile[ty + r*8][tx] = v;
    }
    __syncthreads();
    #pragma unroll
    for (int r = 0; r < 4; r++) {
        int cl = ty + r*8;
        long idx = (long)(c0 + cl)*Hd + k0 + tx;
        split_store(g_Whi, g_Wlo, idx, tile[tx][cl]);
    }
}

// -------- 2. batched cls GEMVs ----------------------------------------------
__global__ __launch_bounds__(128) void k_cls2(const float* __restrict__ seq,
                                              const float* __restrict__ nafW,
                                              const float* __restrict__ nafb,
                                              const float* __restrict__ clsW,
                                              const float* __restrict__ clsb) {
    __shared__ float xs[4][64][16];
    __shared__ float red[4][32][16];
    int m = blockIdx.y;
    const float* W    = m ? clsW : nafW;
    const float* bias = m ? clsb : nafb;
    int tid = threadIdx.x;
    int lane = tid & 31, ks = tid >> 5;

    float acc[16];
    #pragma unroll
    for (int b = 0; b < 16; b++) acc[b] = 0.0f;

    int colg = blockIdx.x*32 + lane;
    for (int t = 0; t < 4; t++) {
        __syncthreads();
        #pragma unroll
        for (int io = 0; io < 32; io++) {
            int flat = io*128 + tid;
            int b    = flat >> 8;
            int rem  = flat & 255;
            int ks2  = rem >> 6;
            int kk   = rem & 63;
            xs[ks2][kk][b] = seq[(long)b*Ss*Hd + ks2*256 + t*64 + kk];
        }
        __syncthreads();
        #pragma unroll 8
        for (int kk = 0; kk < 64; kk++) {
            float w = W[(ks*256 + t*64 + kk)*Hd + colg];
            #pragma unroll
            for (int b2 = 0; b2 < 8; b2++) {
                float2 x2 = *(const float2*)&xs[ks][kk][b2*2];
                acc[2*b2]   = fmaf(x2.x, w, acc[2*b2]);
                acc[2*b2+1] = fmaf(x2.y, w, acc[2*b2+1]);
            }
        }
    }
    #pragma unroll
    for (int b = 0; b < 16; b++) red[ks][lane][b] = acc[b];
    __syncthreads();
    #pragma unroll
    for (int q = 0; q < 4; q++) {
        int o = q*128 + tid;
        int c = o & 31;
        int b = (o >> 5) & 15;
        float v = red[0][c][b] + red[1][c][b] + red[2][c][b] + red[3][c][b];
        int cg = blockIdx.x*32 + c;
        v += bias[cg];
        if (m == 0) {
            long row = (long)(b*Kk + g_n[b])*Hd;
            split_store(g_Xhi, g_Xlo, row + cg, v);
        } else {
            g_cls_hidden[b*Hd + cg] = tanh_fast(v);
        }
    }
}

// -------- 3. tensor-core GEMM via mma.sync bf16 two-term split --------------
// C(512x3072) = X(512x1024) @ Wcat(1024x3072), Wcat stored transposed [n][k].
// CTA 256 thr = 8 warps (4 m x 2 n), tile 128x128, k-chunk 32.
// smem rows padded to 80B for conflict-free ldmatrix.
#define ROWB 80
__global__ __launch_bounds__(256) void k_gemm_mma(const float* __restrict__ node_b,
                                                  const float* __restrict__ edge_b) {
    __shared__ __align__(16) char sm[4 * 128 * ROWB];   // Xhi|Xlo|Whi|Wlo, 40KB
    const int T_XHI = 0, T_XLO = 128*ROWB, T_WHI = 2*128*ROWB, T_WLO = 3*128*ROWB;

    int tid  = threadIdx.x;
    int wid  = tid >> 5, lane = tid & 31;
    int wm   = wid & 3;          // warp m index: rows wm*32 .. +31
    int wn   = wid >> 2;         // warp n index: cols wn*64 .. +63
    int bm   = blockIdx.y, bn = blockIdx.x;

    const char* gX = (const char*)g_Xhi + (long)bm*128*2048;
    const char* gXl = (const char*)g_Xlo + (long)bm*128*2048;
    const char* gW = (const char*)g_Whi + (long)bn*128*2048;
    const char* gWl = (const char*)g_Wlo + (long)bn*128*2048;

    uint32_t smb = smem_u32(sm);

    float acc[2][8][4];
    #pragma unroll
    for (int mt = 0; mt < 2; mt++)
        #pragma unroll
        for (int nt = 0; nt < 8; nt++)
            #pragma unroll
            for (int q = 0; q < 4; q++) acc[mt][nt][q] = 0.0f;

    // ldmatrix per-lane addresses (byte offsets within a tile)
    int a_row  = wm*32 + (lane & 15);              // + mt*16
    int a_koff = (lane >> 4) * 16;                 // + ks*32
    int b_row  = wn*64 + (lane & 7);               // + nt*8
    int b_koff = ((lane >> 3) & 1) * 16;           // + ks*32 (lanes 16-31 don't care)

    for (int ch = 0; ch < 32; ch++) {
        // ---- load 4 tiles (128 rows x 64B each) ----
        long gk = (long)ch * 64;
        #pragma unroll
        for (int it = 0; it < 2; it++) {
            int cidx = tid + it*256;
            int r    = cidx >> 2;
            int cq   = (cidx & 3) * 16;
            int so   = r*ROWB + cq;
            long go  = (long)r*2048 + gk + cq;
            *(uint4*)(sm + T_XHI + so) = *(const uint4*)(gX  + go);
            *(uint4*)(sm + T_XLO + so) = *(const uint4*)(gXl + go);
            *(uint4*)(sm + T_WHI + so) = *(const uint4*)(gW  + go);
            *(uint4*)(sm + T_WLO + so) = *(const uint4*)(gWl + go);
        }
        __syncthreads();

        #pragma unroll
        for (int ks = 0; ks < 2; ks++) {
            uint32_t ahi[2][4], alo[2][4];
            #pragma unroll
            for (int mt = 0; mt < 2; mt++) {
                uint32_t ao = (uint32_t)((a_row + mt*16)*ROWB + ks*32 + a_koff);
                ldsm_x4(ahi[mt][0], ahi[mt][1], ahi[mt][2], ahi[mt][3], smb + T_XHI + ao);
                ldsm_x4(alo[mt][0], alo[mt][1], alo[mt][2], alo[mt][3], smb + T_XLO + ao);
            }
            #pragma unroll
            for (int nt = 0; nt < 8; nt++) {
                uint32_t bo = (uint32_t)((b_row + nt*8)*ROWB + ks*32 + b_koff);
                uint32_t bhi[2], blo[2];
                ldsm_x2(bhi[0], bhi[1], smb + T_WHI + bo);
                ldsm_x2(blo[0], blo[1], smb + T_WLO + bo);
                #pragma unroll
                for (int mt = 0; mt < 2; mt++) {
                    mma16816(acc[mt][nt], ahi[mt], bhi);
                    mma16816(acc[mt][nt], ahi[mt], blo);
                    mma16816(acc[mt][nt], alo[mt], bhi);
                }
            }
        }
        __syncthreads();
    }

    // ---- epilogue: fragment -> gmem with per-region bias/activation ----
    int g = lane >> 2, t = lane & 3;
    int region = bn >> 3;                 // 8 CTAs (x128 cols) per 1024-col region
    #pragma unroll
    for (int mt = 0; mt < 2; mt++) {
        #pragma unroll
        for (int nt = 0; nt < 8; nt++) {
            int col = bn*128 + wn*64 + nt*8 + t*2;
            #pragma unroll
            for (int half = 0; half < 2; half++) {
                int row = bm*128 + wm*32 + mt*16 + g + half*8;
                float v0 = acc[mt][nt][half*2 + 0];
                float v1 = acc[mt][nt][half*2 + 1];
                if (region == 0) {
                    float2 o = make_float2(tanh_fast(v0 + node_b[col]),
                                           tanh_fast(v1 + node_b[col+1]));
                    *(float2*)&g_node_hidden[(long)row*Hd + col] = o;
                } else if (region == 1) {
                    int h = col - Hd;
                    float2 o = make_float2(v0 + edge_b[h], v1 + edge_b[h+1]);
                    *(float2*)&g_Aj[(long)row*Hd + h] = o;
                } else {
                    int h = col - 2*Hd;
                    *(float2*)&g_Ai[(long)row*Hd + h] = make_float2(v0, v1);
                }
            }
        }
    }
}

// -------- 4. cls + node logits ----------------------------------------------
__global__ void k_headout(const float* __restrict__ clsoW, const float* __restrict__ clsob,
                          const float* __restrict__ noW,  const float* __restrict__ nob,
                          float* __restrict__ out) {
    __shared__ float red[8];
    int blk = blockIdx.x;
    const float *src, *oW, *ob;
    long obase;
    if (blk < 16) { src = g_cls_hidden + (long)blk*Hd; oW = clsoW; ob = clsob; obase = blk*2; }
    else { int r = blk - 16; src = g_node_hidden + (long)r*Hd; oW = noW; ob = nob; obase = 32 + r*2; }
    float a0 = 0.f, a1 = 0.f;
    #pragma unroll
    for (int u = 0; u < Hd/128; u++) {
        int h = threadIdx.x + u*128;
        float t = src[h];
        a0 = fmaf(t, oW[2*h  ], a0);
        a1 = fmaf(t, oW[2*h+1], a1);
    }
    block_reduce2(a0, a1, red);
    if (threadIdx.x == 0) {
        out[obase]     = a0 + ob[0];
        out[obase + 1] = a1 + ob[1];
    }
}

// -------- 5. fill edge slots with the invalid-edge constant -----------------
__global__ void k_fill(const float* __restrict__ eb, const float* __restrict__ oW,
                       const float* __restrict__ ob, float* __restrict__ out) {
    __shared__ float red[8];
    __shared__ float cst[2];
    float a0 = 0.f, a1 = 0.f;
    #pragma unroll
    for (int u = 0; u < Hd/128; u++) {
        int h = threadIdx.x + u*128;
        float t = tanh_fast(eb[h]);
        a0 = fmaf(t, oW[2*h  ], a0);
        a1 = fmaf(t, oW[2*h+1], a1);
    }
    block_reduce2(a0, a1, red);
    if (threadIdx.x == 0) { cst[0] = a0 + ob[0]; cst[1] = a1 + ob[1]; }
    __syncthreads();
    float c0 = cst[0], c1 = cst[1];
    long base = 32 + Bb*Kk*2 + (long)blockIdx.x * 1024;
    #pragma unroll
    for (int i = 0; i < 8; i++) {
        int o = i*128 + threadIdx.x;
        out[base + o] = (o & 1) ? c1 : c0;
    }
}

// -------- 6. valid edge logits ----------------------------------------------
__global__ void k_edge(const float* __restrict__ oW, const float* __restrict__ ob,
                       float* __restrict__ out) {
    __shared__ float red[8];
    int e = blockIdx.x, b = blockIdx.y;
    int m = g_n[b] + 1;
    if (e >= m*m) return;
    int i = min(e / m, Kk - 1);
    int j = min(e % m, Kk - 1);
    const float* aj = &g_Aj[(long)(b*Kk + j)*Hd];
    const float* ai = &g_Ai[(long)(b*Kk + i)*Hd];
    float a0 = 0.f, a1 = 0.f;
    #pragma unroll
    for (int u = 0; u < Hd/128; u++) {
        int h = threadIdx.x + u*128;
        float t = tanh_fast(aj[h] + ai[h]);
        a0 = fmaf(t, oW[2*h  ], a0);
        a1 = fmaf(t, oW[2*h+1], a1);
    }
    block_reduce2(a0, a1, red);
    if (threadIdx.x == 0) {
        long base = 32 + Bb*Kk*2 + ((long)b*Ee + e)*2;
        out[base]     = a0 + ob[0];
        out[base + 1] = a1 + ob[1];
    }
}

// ---------------------------------------------------------------------------
extern "C" void kernel_launch(void* const* d_in, const int* in_sizes, int n_in,
                              void* d_out, int out_size) {
    const float* seq   = (const float*)d_in[0];
    const int*   P     = (const int*)d_in[1];
    const float* nafW  = (const float*)d_in[2];
    const float* nafb  = (const float*)d_in[3];
    const float* clsW  = (const float*)d_in[4];
    const float* clsb  = (const float*)d_in[5];
    const float* clsoW = (const float*)d_in[6];
    const float* clsob = (const float*)d_in[7];
    const float* ndW   = (const float*)d_in[8];
    const float* ndb   = (const float*)d_in[9];
    const float* noW   = (const float*)d_in[10];
    const float* nob   = (const float*)d_in[11];
    const float* edW   = (const float*)d_in[12];
    const float* edb   = (const float*)d_in[13];
    const float* eoW   = (const float*)d_in[14];
    const float* eob   = (const float*)d_in[15];
    float* out = (float*)d_out;

    k_meta<<<dim3(Kk, Bb), 256>>>(seq, P);                          // idx 0
    k_wsplit<<<dim3(NCAT/32, Hd/32), dim3(32, 8)>>>(ndW, edW);      // idx 1
    k_cls2<<<dim3(Hd/32, 2), 128>>>(seq, nafW, nafb, clsW, clsb);   // idx 2
    k_gemm_mma<<<dim3(NCAT/128, 512/128), 256>>>(ndb, edb);         // idx 3 (ncu)
    k_headout<<<16 + 512, 128>>>(clsoW, clsob, noW, nob, out);      // idx 4
    k_fill<<<Bb*Ee*2/1024, 128>>>(edb, eoW, eob, out);              // idx 5
    k_edge<<<dim3(Ee, Bb), 128>>>(eoW, eob, out);                   // idx 6
}

// round 6
// speedup vs baseline: 2.0905x; 1.1214x over previous
#include <cuda_runtime.h>
#include <cuda_bf16.h>
#include <cstdint>

#define Hd   1024
#define Bb   16
#define Ss   512
#define Kk   32
#define Ee   1024
#define NCAT 3072

// ---------------- scratch ----------------------------------------------------
__device__ __nv_bfloat16 g_Xhi[512*Hd];
__device__ __nv_bfloat16 g_Xlo[512*Hd];
__device__ __nv_bfloat16 g_Whi[NCAT*Hd];    // Wcat^T hi  [3072 n][1024 k]
__device__ __nv_bfloat16 g_Wlo[NCAT*Hd];
__device__ float g_node_hidden[512*Hd];
__device__ float g_Aj[512*Hd];
__device__ float g_Ai[512*Hd];
__device__ float g_cls_hidden[Bb*Hd];
__device__ int   g_n[Bb];

// ---------------- helpers ----------------------------------------------------
__device__ __forceinline__ float tanh_fast(float x) {
    float e = __expf(2.0f * x);
    return 1.0f - __fdividef(2.0f, e + 1.0f);
}

__device__ __forceinline__ uint32_t smem_u32(const void* p) {
    uint32_t a;
    asm("{ .reg .u64 t; cvta.to.shared.u64 t, %1; cvt.u32.u64 %0, t; }" : "=r"(a) : "l"(p));
    return a;
}

__device__ __forceinline__ void cp16(uint32_t saddr, const void* g) {
    asm volatile("cp.async.cg.shared.global [%0], [%1], 16;" :: "r"(saddr), "l"(g));
}
__device__ __forceinline__ void cp_commit() {
    asm volatile("cp.async.commit_group;");
}
template <int N>
__device__ __forceinline__ void cp_wait() {
    asm volatile("cp.async.wait_group %0;" :: "n"(N));
}

__device__ __forceinline__ void ldsm_x4(uint32_t& r0, uint32_t& r1, uint32_t& r2,
                                        uint32_t& r3, uint32_t addr) {
    asm volatile("ldmatrix.sync.aligned.m8n8.x4.shared.b16 {%0,%1,%2,%3}, [%4];"
                 : "=r"(r0), "=r"(r1), "=r"(r2), "=r"(r3) : "r"(addr));
}
__device__ __forceinline__ void ldsm_x2(uint32_t& r0, uint32_t& r1, uint32_t addr) {
    asm volatile("ldmatrix.sync.aligned.m8n8.x2.shared.b16 {%0,%1}, [%2];"
                 : "=r"(r0), "=r"(r1) : "r"(addr));
}
__device__ __forceinline__ void mma16816(float* d, const uint32_t* a, const uint32_t* b) {
    asm volatile(
        "mma.sync.aligned.m16n8k16.row.col.f32.bf16.bf16.f32 "
        "{%0,%1,%2,%3}, {%4,%5,%6,%7}, {%8,%9}, {%0,%1,%2,%3};"
        : "+f"(d[0]), "+f"(d[1]), "+f"(d[2]), "+f"(d[3])
        : "r"(a[0]), "r"(a[1]), "r"(a[2]), "r"(a[3]), "r"(b[0]), "r"(b[1]));
}

__device__ __forceinline__ void block_reduce2(float& a0, float& a1, float* red) {
    #pragma unroll
    for (int o = 16; o > 0; o >>= 1) {
        a0 += __shfl_down_sync(0xffffffffu, a0, o);
        a1 += __shfl_down_sync(0xffffffffu, a1, o);
    }
    int w = threadIdx.x >> 5;
    if ((threadIdx.x & 31) == 0) { red[2*w] = a0; red[2*w+1] = a1; }
    __syncthreads();
    if (threadIdx.x == 0) {
        a0 = red[0]; a1 = red[1];
        for (int w2 = 1; w2 < (int)(blockDim.x >> 5); w2++) {
            a0 += red[2*w2]; a1 += red[2*w2+1];
        }
    }
}

__device__ __forceinline__ void split_store(__nv_bfloat16* hi, __nv_bfloat16* lo,
                                            long idx, float v) {
    __nv_bfloat16 h = __float2bfloat16(v);
    hi[idx] = h;
    lo[idx] = __float2bfloat16(v - __bfloat162float(h));
}

// -------- 0. segment means -> Xhi/Xlo; g_n ----------------------------------
__global__ void k_meta(const float* __restrict__ seq, const int* __restrict__ P) {
    int k = blockIdx.x, b = blockIdx.y;
    int n = 0;
    #pragma unroll
    for (int j = 0; j < Kk - 1; j++) n += (P[b*Kk + 1 + j] > 0);
    if (k == 0 && threadIdx.x == 0) g_n[b] = n;
    long row = (long)(b*Kk + k) * Hd;
    if (k < n) {
        int end   = P[b*Kk + 1 + k];
        int start = (k == 0) ? 1 : (P[b*Kk + k] + 1);
        float inv = 1.0f / (float)(end - start + 1);
        #pragma unroll
        for (int u = 0; u < Hd/256; u++) {
            int h = threadIdx.x + u*256;
            float s = 0.0f;
            for (int p = start; p <= end; p++)
                s += seq[((long)b*Ss + p)*Hd + h];
            split_store(g_Xhi, g_Xlo, row + h, s * inv);
        }
    } else {
        #pragma unroll
        for (int u = 0; u < Hd/256; u++) {
            int h = threadIdx.x + u*256;
            g_Xhi[row + h] = __float2bfloat16(0.f);
            g_Xlo[row + h] = __float2bfloat16(0.f);
        }
    }
}

// -------- 1. transposed hi/lo weight build ----------------------------------
__global__ void k_wsplit(const float* __restrict__ nodeW, const float* __restrict__ eW) {
    __shared__ float tile[32][33];
    int tx = threadIdx.x, ty = threadIdx.y;
    int c0 = blockIdx.x * 32, k0 = blockIdx.y * 32;
    #pragma unroll
    for (int r = 0; r < 4; r++) {
        int kk = k0 + ty + r*8;
        int c  = c0 + tx;
        float v;
        if (c < Hd) {
            v = nodeW[kk*Hd + c];
        } else if (c < 2*Hd) {
            int h = c - Hd;
            v = eW[kk*Hd + h] + eW[(2*Hd + kk)*Hd + h];
        } else {
            int h = c - 2*Hd;
            v = eW[(Hd + kk)*Hd + h] - eW[(2*Hd + kk)*Hd + h];
        }
        tile[ty + r*8][tx] = v;
    }
    __syncthreads();
    #pragma unroll
    for (int r = 0; r < 4; r++) {
        int cl = ty + r*8;
        long idx = (long)(c0 + cl)*Hd + k0 + tx;
        split_store(g_Whi, g_Wlo, idx, tile[tx][cl]);
    }
}

// -------- 2. batched cls GEMVs ----------------------------------------------
__global__ __launch_bounds__(128) void k_cls2(const float* __restrict__ seq,
                                              const float* __restrict__ nafW,
                                              const float* __restrict__ nafb,
                                              const float* __restrict__ clsW,
                                              const float* __restrict__ clsb) {
    __shared__ float xs[4][64][16];
    __shared__ float red[4][32][16];
    int m = blockIdx.y;
    const float* W    = m ? clsW : nafW;
    const float* bias = m ? clsb : nafb;
    int tid = threadIdx.x;
    int lane = tid & 31, ks = tid >> 5;

    float acc[16];
    #pragma unroll
    for (int b = 0; b < 16; b++) acc[b] = 0.0f;

    int colg = blockIdx.x*32 + lane;
    for (int t = 0; t < 4; t++) {
        __syncthreads();
        #pragma unroll
        for (int io = 0; io < 32; io++) {
            int flat = io*128 + tid;
            int b    = flat >> 8;
            int rem  = flat & 255;
            int ks2  = rem >> 6;
            int kk   = rem & 63;
            xs[ks2][kk][b] = seq[(long)b*Ss*Hd + ks2*256 + t*64 + kk];
        }
        __syncthreads();
        #pragma unroll 8
        for (int kk = 0; kk < 64; kk++) {
            float w = W[(ks*256 + t*64 + kk)*Hd + colg];
            #pragma unroll
            for (int b2 = 0; b2 < 8; b2++) {
                float2 x2 = *(const float2*)&xs[ks][kk][b2*2];
                acc[2*b2]   = fmaf(x2.x, w, acc[2*b2]);
                acc[2*b2+1] = fmaf(x2.y, w, acc[2*b2+1]);
            }
        }
    }
    #pragma unroll
    for (int b = 0; b < 16; b++) red[ks][lane][b] = acc[b];
    __syncthreads();
    #pragma unroll
    for (int q = 0; q < 4; q++) {
        int o = q*128 + tid;
        int c = o & 31;
        int b = (o >> 5) & 15;
        float v = red[0][c][b] + red[1][c][b] + red[2][c][b] + red[3][c][b];
        int cg = blockIdx.x*32 + c;
        v += bias[cg];
        if (m == 0) {
            long row = (long)(b*Kk + g_n[b])*Hd;
            split_store(g_Xhi, g_Xlo, row + cg, v);
        } else {
            g_cls_hidden[b*Hd + cg] = tanh_fast(v);
        }
    }
}

// -------- 3. tensor-core GEMM, cp.async double-buffered ---------------------
// C(512x3072) = X(512x1024) @ Wcat(1024x3072). CTA 256 thr, tile 128x128,
// k-chunk 32, 2 stages. smem rows padded to 80B.
#define ROWB 80
#define TILE_B (128*ROWB)
#define STAGE_B (4*TILE_B)     // Xhi|Xlo|Whi|Wlo = 40960 B per stage
__global__ __launch_bounds__(256) void k_gemm_mma(const float* __restrict__ node_b,
                                                  const float* __restrict__ edge_b) {
    extern __shared__ __align__(16) char sm[];   // 2 * STAGE_B
    const int T_XHI = 0, T_XLO = TILE_B, T_WHI = 2*TILE_B, T_WLO = 3*TILE_B;

    int tid  = threadIdx.x;
    int wid  = tid >> 5, lane = tid & 31;
    int wm   = wid & 3;
    int wn   = wid >> 2;
    int bm   = blockIdx.y, bn = blockIdx.x;

    const char* gX  = (const char*)g_Xhi + (long)bm*128*2048;
    const char* gXl = (const char*)g_Xlo + (long)bm*128*2048;
    const char* gW  = (const char*)g_Whi + (long)bn*128*2048;
    const char* gWl = (const char*)g_Wlo + (long)bn*128*2048;

    uint32_t smb = smem_u32(sm);

    // per-thread load coordinates (8 x 16B chunks per stage: 2 per tile)
    int l_r0 = tid >> 2;                 // chunk 0 row
    int l_c0 = (tid & 3) * 16;
    int l_r1 = (tid + 256) >> 2;         // chunk 1 row
    int l_c1 = ((tid + 256) & 3) * 16;

    auto load_stage = [&](int ch, int st) {
        long gk = (long)ch * 64;
        uint32_t sb = smb + st*STAGE_B;
        int so0 = l_r0*ROWB + l_c0;
        int so1 = l_r1*ROWB + l_c1;
        long go0 = (long)l_r0*2048 + gk + l_c0;
        long go1 = (long)l_r1*2048 + gk + l_c1;
        cp16(sb + T_XHI + so0, gX  + go0); cp16(sb + T_XHI + so1, gX  + go1);
        cp16(sb + T_XLO + so0, gXl + go0); cp16(sb + T_XLO + so1, gXl + go1);
        cp16(sb + T_WHI + so0, gW  + go0); cp16(sb + T_WHI + so1, gW  + go1);
        cp16(sb + T_WLO + so0, gWl + go0); cp16(sb + T_WLO + so1, gWl + go1);
    };

    float acc[2][8][4];
    #pragma unroll
    for (int mt = 0; mt < 2; mt++)
        #pragma unroll
        for (int nt = 0; nt < 8; nt++)
            #pragma unroll
            for (int q = 0; q < 4; q++) acc[mt][nt][q] = 0.0f;

    int a_row  = wm*32 + (lane & 15);
    int a_koff = (lane >> 4) * 16;
    int b_row  = wn*64 + (lane & 7);
    int b_koff = ((lane >> 3) & 1) * 16;

    load_stage(0, 0); cp_commit();
    load_stage(1, 1); cp_commit();

    for (int ch = 0; ch < 32; ch++) {
        cp_wait<1>();
        __syncthreads();
        int st = ch & 1;
        uint32_t sbase = smb + st*STAGE_B;

        #pragma unroll
        for (int ks = 0; ks < 2; ks++) {
            uint32_t ahi[2][4], alo[2][4];
            #pragma unroll
            for (int mt = 0; mt < 2; mt++) {
                uint32_t ao = (uint32_t)((a_row + mt*16)*ROWB + ks*32 + a_koff);
                ldsm_x4(ahi[mt][0], ahi[mt][1], ahi[mt][2], ahi[mt][3], sbase + T_XHI + ao);
                ldsm_x4(alo[mt][0], alo[mt][1], alo[mt][2], alo[mt][3], sbase + T_XLO + ao);
            }
            #pragma unroll
            for (int nt = 0; nt < 8; nt++) {
                uint32_t bo = (uint32_t)((b_row + nt*8)*ROWB + ks*32 + b_koff);
                uint32_t bhi[2], blo[2];
                ldsm_x2(bhi[0], bhi[1], sbase + T_WHI + bo);
                ldsm_x2(blo[0], blo[1], sbase + T_WLO + bo);
                #pragma unroll
                for (int mt = 0; mt < 2; mt++) {
                    mma16816(acc[mt][nt], ahi[mt], bhi);
                    mma16816(acc[mt][nt], ahi[mt], blo);
                    mma16816(acc[mt][nt], alo[mt], bhi);
                }
            }
        }
        __syncthreads();                       // all warps done reading stage st
        if (ch + 2 < 32) load_stage(ch + 2, st);
        cp_commit();                           // empty groups at tail keep count
    }

    // ---- epilogue ----
    int g = lane >> 2, t = lane & 3;
    int region = bn >> 3;
    #pragma unroll
    for (int mt = 0; mt < 2; mt++) {
        #pragma unroll
        for (int nt = 0; nt < 8; nt++) {
            int col = bn*128 + wn*64 + nt*8 + t*2;
            #pragma unroll
            for (int half = 0; half < 2; half++) {
                int row = bm*128 + wm*32 + mt*16 + g + half*8;
                float v0 = acc[mt][nt][half*2 + 0];
                float v1 = acc[mt][nt][half*2 + 1];
                if (region == 0) {
                    float2 o = make_float2(tanh_fast(v0 + node_b[col]),
                                           tanh_fast(v1 + node_b[col+1]));
                    *(float2*)&g_node_hidden[(long)row*Hd + col] = o;
                } else if (region == 1) {
                    int h = col - Hd;
                    float2 o = make_float2(v0 + edge_b[h], v1 + edge_b[h+1]);
                    *(float2*)&g_Aj[(long)row*Hd + h] = o;
                } else {
                    int h = col - 2*Hd;
                    *(float2*)&g_Ai[(long)row*Hd + h] = make_float2(v0, v1);
                }
            }
        }
    }
}

// -------- 4. cls + node logits ----------------------------------------------
__global__ void k_headout(const float* __restrict__ clsoW, const float* __restrict__ clsob,
                          const float* __restrict__ noW,  const float* __restrict__ nob,
                          float* __restrict__ out) {
    __shared__ float red[8];
    int blk = blockIdx.x;
    const float *src, *oW, *ob;
    long obase;
    if (blk < 16) { src = g_cls_hidden + (long)blk*Hd; oW = clsoW; ob = clsob; obase = blk*2; }
    else { int r = blk - 16; src = g_node_hidden + (long)r*Hd; oW = noW; ob = nob; obase = 32 + r*2; }
    float a0 = 0.f, a1 = 0.f;
    #pragma unroll
    for (int u = 0; u < Hd/128; u++) {
        int h = threadIdx.x + u*128;
        float t = src[h];
        a0 = fmaf(t, oW[2*h  ], a0);
        a1 = fmaf(t, oW[2*h+1], a1);
    }
    block_reduce2(a0, a1, red);
    if (threadIdx.x == 0) {
        out[obase]     = a0 + ob[0];
        out[obase + 1] = a1 + ob[1];
    }
}

// -------- 5. fill invalid-edge constant -------------------------------------
__global__ void k_fill(const float* __restrict__ eb, const float* __restrict__ oW,
                       const float* __restrict__ ob, float* __restrict__ out) {
    __shared__ float red[8];
    __shared__ float cst[2];
    float a0 = 0.f, a1 = 0.f;
    #pragma unroll
    for (int u = 0; u < Hd/128; u++) {
        int h = threadIdx.x + u*128;
        float t = tanh_fast(eb[h]);
        a0 = fmaf(t, oW[2*h  ], a0);
        a1 = fmaf(t, oW[2*h+1], a1);
    }
    block_reduce2(a0, a1, red);
    if (threadIdx.x == 0) { cst[0] = a0 + ob[0]; cst[1] = a1 + ob[1]; }
    __syncthreads();
    float c0 = cst[0], c1 = cst[1];
    long base = 32 + Bb*Kk*2 + (long)blockIdx.x * 1024;
    #pragma unroll
    for (int i = 0; i < 8; i++) {
        int o = i*128 + threadIdx.x;
        out[base + o] = (o & 1) ? c1 : c0;
    }
}

// -------- 6. valid edge logits ----------------------------------------------
__global__ void k_edge(const float* __restrict__ oW, const float* __restrict__ ob,
                       float* __restrict__ out) {
    __shared__ float red[8];
    int e = blockIdx.x, b = blockIdx.y;
    int m = g_n[b] + 1;
    if (e >= m*m) return;
    int i = min(e / m, Kk - 1);
    int j = min(e % m, Kk - 1);
    const float* aj = &g_Aj[(long)(b*Kk + j)*Hd];
    const float* ai = &g_Ai[(long)(b*Kk + i)*Hd];
    float a0 = 0.f, a1 = 0.f;
    #pragma unroll
    for (int u = 0; u < Hd/128; u++) {
        int h = threadIdx.x + u*128;
        float t = tanh_fast(aj[h] + ai[h]);
        a0 = fmaf(t, oW[2*h  ], a0);
        a1 = fmaf(t, oW[2*h+1], a1);
    }
    block_reduce2(a0, a1, red);
    if (threadIdx.x == 0) {
        long base = 32 + Bb*Kk*2 + ((long)b*Ee + e)*2;
        out[base]     = a0 + ob[0];
        out[base + 1] = a1 + ob[1];
    }
}

// ---------------------------------------------------------------------------
extern "C" void kernel_launch(void* const* d_in, const int* in_sizes, int n_in,
                              void* d_out, int out_size) {
    const float* seq   = (const float*)d_in[0];
    const int*   P     = (const int*)d_in[1];
    const float* nafW  = (const float*)d_in[2];
    const float* nafb  = (const float*)d_in[3];
    const float* clsW  = (const float*)d_in[4];
    const float* clsb  = (const float*)d_in[5];
    const float* clsoW = (const float*)d_in[6];
    const float* clsob = (const float*)d_in[7];
    const float* ndW   = (const float*)d_in[8];
    const float* ndb   = (const float*)d_in[9];
    const float* noW   = (const float*)d_in[10];
    const float* nob   = (const float*)d_in[11];
    const float* edW   = (const float*)d_in[12];
    const float* edb   = (const float*)d_in[13];
    const float* eoW   = (const float*)d_in[14];
    const float* eob   = (const float*)d_in[15];
    float* out = (float*)d_out;

    cudaFuncSetAttribute(k_gemm_mma, cudaFuncAttributeMaxDynamicSharedMemorySize,
                         2*STAGE_B);

    k_meta<<<dim3(Kk, Bb), 256>>>(seq, P);                              // idx 0
    k_wsplit<<<dim3(NCAT/32, Hd/32), dim3(32, 8)>>>(ndW, edW);          // idx 1
    k_cls2<<<dim3(Hd/32, 2), 128>>>(seq, nafW, nafb, clsW, clsb);       // idx 2
    k_gemm_mma<<<dim3(NCAT/128, 512/128), 256, 2*STAGE_B>>>(ndb, edb);  // idx 3 (ncu)
    k_headout<<<16 + 512, 128>>>(clsoW, clsob, noW, nob, out);          // idx 4
    k_fill<<<Bb*Ee*2/1024, 128>>>(edb, eoW, eob, out);                  // idx 5
    k_edge<<<dim3(Ee, Bb), 128>>>(eoW, eob, out);                       // idx 6
}

// round 7
// speedup vs baseline: 2.8199x; 1.3489x over previous
#include <cuda_runtime.h>
#include <cuda_fp16.h>
#include <cstdint>

#define Hd   1024
#define Bb   16
#define Ss   512
#define Kk   32
#define Ee   1024
#define NCAT 3072

// ---------------- scratch ----------------------------------------------------
__device__ __half g_Xh[512*Hd];         // full_nodes fp16  [512][1024]
__device__ __half g_Wh[NCAT*Hd];        // Wcat^T fp16      [3072 n][1024 k]
__device__ float g_node_hidden[512*Hd];
__device__ float g_Aj[512*Hd];          // edge bias folded in
__device__ float g_Ai[512*Hd];
__device__ float g_cls_hidden[Bb*Hd];
__device__ float g_invconst[2];         // invalid-edge logits
__device__ int   g_n[Bb];

// ---------------- helpers ----------------------------------------------------
__device__ __forceinline__ float tanh_fast(float x) {
    float e = __expf(2.0f * x);
    return 1.0f - __fdividef(2.0f, e + 1.0f);
}

__device__ __forceinline__ uint32_t smem_u32(const void* p) {
    uint32_t a;
    asm("{ .reg .u64 t; cvta.to.shared.u64 t, %1; cvt.u32.u64 %0, t; }" : "=r"(a) : "l"(p));
    return a;
}

__device__ __forceinline__ void cp16(uint32_t saddr, const void* g) {
    asm volatile("cp.async.cg.shared.global [%0], [%1], 16;" :: "r"(saddr), "l"(g));
}
__device__ __forceinline__ void cp_commit() {
    asm volatile("cp.async.commit_group;");
}
template <int N>
__device__ __forceinline__ void cp_wait() {
    asm volatile("cp.async.wait_group %0;" :: "n"(N));
}

__device__ __forceinline__ void ldsm_x4(uint32_t& r0, uint32_t& r1, uint32_t& r2,
                                        uint32_t& r3, uint32_t addr) {
    asm volatile("ldmatrix.sync.aligned.m8n8.x4.shared.b16 {%0,%1,%2,%3}, [%4];"
                 : "=r"(r0), "=r"(r1), "=r"(r2), "=r"(r3) : "r"(addr));
}
__device__ __forceinline__ void ldsm_x2(uint32_t& r0, uint32_t& r1, uint32_t addr) {
    asm volatile("ldmatrix.sync.aligned.m8n8.x2.shared.b16 {%0,%1}, [%2];"
                 : "=r"(r0), "=r"(r1) : "r"(addr));
}
__device__ __forceinline__ void mma16816h(float* d, const uint32_t* a, const uint32_t* b) {
    asm volatile(
        "mma.sync.aligned.m16n8k16.row.col.f32.f16.f16.f32 "
        "{%0,%1,%2,%3}, {%4,%5,%6,%7}, {%8,%9}, {%0,%1,%2,%3};"
        : "+f"(d[0]), "+f"(d[1]), "+f"(d[2]), "+f"(d[3])
        : "r"(a[0]), "r"(a[1]), "r"(a[2]), "r"(a[3]), "r"(b[0]), "r"(b[1]));
}

// works for blockDim 128 or 256 (red must hold 2*nwarps floats)
__device__ __forceinline__ void block_reduce2(float& a0, float& a1, float* red) {
    #pragma unroll
    for (int o = 16; o > 0; o >>= 1) {
        a0 += __shfl_down_sync(0xffffffffu, a0, o);
        a1 += __shfl_down_sync(0xffffffffu, a1, o);
    }
    int w = threadIdx.x >> 5;
    if ((threadIdx.x & 31) == 0) { red[2*w] = a0; red[2*w+1] = a1; }
    __syncthreads();
    if (threadIdx.x == 0) {
        a0 = red[0]; a1 = red[1];
        for (int w2 = 1; w2 < (int)(blockDim.x >> 5); w2++) {
            a0 += red[2*w2]; a1 += red[2*w2+1];
        }
    }
}

// -------- 0. segment means -> Xh; g_n ---------------------------------------
__global__ void k_meta(const float* __restrict__ seq, const int* __restrict__ P) {
    int k = blockIdx.x, b = blockIdx.y;
    int n = 0;
    #pragma unroll
    for (int j = 0; j < Kk - 1; j++) n += (P[b*Kk + 1 + j] > 0);
    if (k == 0 && threadIdx.x == 0) g_n[b] = n;
    long row = (long)(b*Kk + k) * Hd;
    if (k < n) {
        int end   = P[b*Kk + 1 + k];
        int start = (k == 0) ? 1 : (P[b*Kk + k] + 1);
        float inv = 1.0f / (float)(end - start + 1);
        #pragma unroll
        for (int u = 0; u < Hd/256; u++) {
            int h = threadIdx.x + u*256;
            float s = 0.0f;
            for (int p = start; p <= end; p++)
                s += seq[((long)b*Ss + p)*Hd + h];
            g_Xh[row + h] = __float2half(s * inv);
        }
    } else {
        #pragma unroll
        for (int u = 0; u < Hd/256; u++)
            g_Xh[row + threadIdx.x + u*256] = __float2half(0.f);
    }
}

// -------- 1. transposed fp16 weight build + invalid-edge constant -----------
// flat grid: blocks [0,3072) = 32x32 transpose tiles, block 3072 = invconst.
__global__ __launch_bounds__(256) void k_wsplit(const float* __restrict__ nodeW,
                                                const float* __restrict__ eW,
                                                const float* __restrict__ eb,
                                                const float* __restrict__ eoW,
                                                const float* __restrict__ eob) {
    int blk = blockIdx.x;
    int t = threadIdx.x;
    if (blk < 3072) {
        __shared__ float tile[32][33];
        int tx = t & 31, ty = t >> 5;
        int c0 = (blk % 96) * 32, k0 = (blk / 96) * 32;
        #pragma unroll
        for (int r = 0; r < 4; r++) {
            int kk = k0 + ty + r*8;
            int c  = c0 + tx;
            float v;
            if (c < Hd) {
                v = nodeW[kk*Hd + c];
            } else if (c < 2*Hd) {
                int h = c - Hd;
                v = eW[kk*Hd + h] + eW[(2*Hd + kk)*Hd + h];
            } else {
                int h = c - 2*Hd;
                v = eW[(Hd + kk)*Hd + h] - eW[(2*Hd + kk)*Hd + h];
            }
            tile[ty + r*8][tx] = v;
        }
        __syncthreads();
        #pragma unroll
        for (int r = 0; r < 4; r++) {
            int cl = ty + r*8;
            g_Wh[(long)(c0 + cl)*Hd + k0 + tx] = __float2half(tile[tx][cl]);
        }
    } else {
        __shared__ float red[16];
        float a0 = 0.f, a1 = 0.f;
        #pragma unroll
        for (int u = 0; u < Hd/256; u++) {
            int h = t + u*256;
            float v = tanh_fast(eb[h]);
            a0 = fmaf(v, eoW[2*h  ], a0);
            a1 = fmaf(v, eoW[2*h+1], a1);
        }
        block_reduce2(a0, a1, red);
        if (t == 0) { g_invconst[0] = a0 + eob[0]; g_invconst[1] = a1 + eob[1]; }
    }
}

// -------- 2. batched cls GEMVs: naf (m=0) -> Xh row n; cls_hidden (m=1) -----
__global__ __launch_bounds__(128) void k_cls2(const float* __restrict__ seq,
                                              const float* __restrict__ nafW,
                                              const float* __restrict__ nafb,
                                              const float* __restrict__ clsW,
                                              const float* __restrict__ clsb) {
    __shared__ float xs[4][64][16];
    __shared__ float red[4][32][16];
    int m = blockIdx.y;
    const float* W    = m ? clsW : nafW;
    const float* bias = m ? clsb : nafb;
    int tid = threadIdx.x;
    int lane = tid & 31, ks = tid >> 5;

    float acc[16];
    #pragma unroll
    for (int b = 0; b < 16; b++) acc[b] = 0.0f;

    int colg = blockIdx.x*32 + lane;
    for (int t = 0; t < 4; t++) {
        __syncthreads();
        #pragma unroll
        for (int io = 0; io < 32; io++) {
            int flat = io*128 + tid;
            int b    = flat >> 8;
            int rem  = flat & 255;
            int ks2  = rem >> 6;
            int kk   = rem & 63;
            xs[ks2][kk][b] = seq[(long)b*Ss*Hd + ks2*256 + t*64 + kk];
        }
        __syncthreads();
        #pragma unroll 8
        for (int kk = 0; kk < 64; kk++) {
            float w = W[(ks*256 + t*64 + kk)*Hd + colg];
            #pragma unroll
            for (int b2 = 0; b2 < 8; b2++) {
                float2 x2 = *(const float2*)&xs[ks][kk][b2*2];
                acc[2*b2]   = fmaf(x2.x, w, acc[2*b2]);
                acc[2*b2+1] = fmaf(x2.y, w, acc[2*b2+1]);
            }
        }
    }
    #pragma unroll
    for (int b = 0; b < 16; b++) red[ks][lane][b] = acc[b];
    __syncthreads();
    #pragma unroll
    for (int q = 0; q < 4; q++) {
        int o = q*128 + tid;
        int c = o & 31;
        int b = (o >> 5) & 15;
        float v = red[0][c][b] + red[1][c][b] + red[2][c][b] + red[3][c][b];
        int cg = blockIdx.x*32 + c;
        v += bias[cg];
        if (m == 0) {
            g_Xh[(long)(b*Kk + g_n[b])*Hd + cg] = __float2half(v);
        } else {
            g_cls_hidden[b*Hd + cg] = tanh_fast(v);
        }
    }
}

// -------- 3. fp16 tensor GEMM: C(512x3072) = X @ Wcat -----------------------
// Tile M=64, N=128, k-chunk 32, 128 thr (4 warps, 2m x 2n), grid (24, 8).
// Double-buffered cp.async; smem rows padded to 80B.
#define ROWB 80
#define A_OFF 0
#define B_OFF (64*ROWB)
#define STAGE_B ((64+128)*ROWB)    // 15360 B
__global__ __launch_bounds__(128) void k_gemm(const float* __restrict__ node_b,
                                              const float* __restrict__ edge_b) {
    __shared__ __align__(16) char sm[2*STAGE_B];

    int tid  = threadIdx.x;
    int wid  = tid >> 5, lane = tid & 31;
    int wm   = wid & 1;          // 2 warps along M (32 rows each)
    int wn   = wid >> 1;         // 2 warps along N (64 cols each)
    int bn   = blockIdx.x, bm = blockIdx.y;

    const char* gX = (const char*)g_Xh + (long)bm*64*2048;
    const char* gW = (const char*)g_Wh + (long)bn*128*2048;

    uint32_t smb = smem_u32(sm);

    auto load_stage = [&](int ch, int st) {
        long gk = (long)ch * 64;
        uint32_t sb = smb + st*STAGE_B;
        #pragma unroll
        for (int i = 0; i < 6; i++) {
            int idx = tid + i*128;
            if (idx < 256) {
                int r = idx >> 2, c = (idx & 3)*16;
                cp16(sb + A_OFF + r*ROWB + c, gX + (long)r*2048 + gk + c);
            } else {
                int j = idx - 256;
                int r = j >> 2, c = (j & 3)*16;
                cp16(sb + B_OFF + r*ROWB + c, gW + (long)r*2048 + gk + c);
            }
        }
    };

    float acc[2][8][4];
    #pragma unroll
    for (int mt = 0; mt < 2; mt++)
        #pragma unroll
        for (int nt = 0; nt < 8; nt++)
            #pragma unroll
            for (int q = 0; q < 4; q++) acc[mt][nt][q] = 0.0f;

    int a_row  = wm*32 + (lane & 15);
    int a_koff = (lane >> 4) * 16;
    int b_row  = wn*64 + (lane & 7);
    int b_koff = ((lane >> 3) & 1) * 16;

    load_stage(0, 0); cp_commit();
    load_stage(1, 1); cp_commit();

    for (int ch = 0; ch < 32; ch++) {
        cp_wait<1>();
        __syncthreads();
        uint32_t sbase = smb + (ch & 1)*STAGE_B;

        #pragma unroll
        for (int ks = 0; ks < 2; ks++) {
            uint32_t a[2][4];
            #pragma unroll
            for (int mt = 0; mt < 2; mt++) {
                uint32_t ao = (uint32_t)((a_row + mt*16)*ROWB + ks*32 + a_koff);
                ldsm_x4(a[mt][0], a[mt][1], a[mt][2], a[mt][3], sbase + A_OFF + ao);
            }
            #pragma unroll
            for (int nt = 0; nt < 8; nt++) {
                uint32_t bo = (uint32_t)((b_row + nt*8)*ROWB + ks*32 + b_koff);
                uint32_t bf[2];
                ldsm_x2(bf[0], bf[1], sbase + B_OFF + bo);
                #pragma unroll
                for (int mt = 0; mt < 2; mt++)
                    mma16816h(acc[mt][nt], a[mt], bf);
            }
        }
        __syncthreads();
        if (ch + 2 < 32) load_stage(ch + 2, (ch & 1));
        cp_commit();
    }

    // ---- epilogue ----
    int g = lane >> 2, t = lane & 3;
    int region = bn >> 3;           // 0: node_hidden, 1: Aj, 2: Ai
    #pragma unroll
    for (int mt = 0; mt < 2; mt++) {
        #pragma unroll
        for (int nt = 0; nt < 8; nt++) {
            int col = bn*128 + wn*64 + nt*8 + t*2;
            #pragma unroll
            for (int half = 0; half < 2; half++) {
                int row = bm*64 + wm*32 + mt*16 + g + half*8;
                float v0 = acc[mt][nt][half*2 + 0];
                float v1 = acc[mt][nt][half*2 + 1];
                if (region == 0) {
                    float2 o = make_float2(tanh_fast(v0 + node_b[col]),
                                           tanh_fast(v1 + node_b[col+1]));
                    *(float2*)&g_node_hidden[(long)row*Hd + col] = o;
                } else if (region == 1) {
                    int h = col - Hd;
                    float2 o = make_float2(v0 + edge_b[h], v1 + edge_b[h+1]);
                    *(float2*)&g_Aj[(long)row*Hd + h] = o;
                } else {
                    int h = col - 2*Hd;
                    *(float2*)&g_Ai[(long)row*Hd + h] = make_float2(v0, v1);
                }
            }
        }
    }
}

// -------- 4. fused heads: cls [0,16), node [16,528), edges [528, 528+4096) --
// edge blocks handle 4 consecutive e each, caching eoW in smem.
__global__ __launch_bounds__(128) void k_post(const float* __restrict__ clsoW,
                                              const float* __restrict__ clsob,
                                              const float* __restrict__ noW,
                                              const float* __restrict__ nob,
                                              const float* __restrict__ eoW,
                                              const float* __restrict__ eob,
                                              float* __restrict__ out) {
    __shared__ float red[16];
    __shared__ float2 sW[Hd];
    int blk = blockIdx.x;
    int tid = threadIdx.x;

    if (blk < 528) {
        const float *src, *oW, *ob;
        long obase;
        if (blk < 16) { src = g_cls_hidden + (long)blk*Hd; oW = clsoW; ob = clsob; obase = blk*2; }
        else { int r = blk - 16; src = g_node_hidden + (long)r*Hd; oW = noW; ob = nob; obase = 32 + r*2; }
        float a0 = 0.f, a1 = 0.f;
        #pragma unroll
        for (int u = 0; u < Hd/128; u++) {
            int h = tid + u*128;
            float t = src[h];
            a0 = fmaf(t, oW[2*h  ], a0);
            a1 = fmaf(t, oW[2*h+1], a1);
        }
        block_reduce2(a0, a1, red);
        if (tid == 0) { out[obase] = a0 + ob[0]; out[obase + 1] = a1 + ob[1]; }
        return;
    }

    int id = blk - 528;               // 0..4095
    int b  = id >> 8;
    int e0 = (id & 255) * 4;
    #pragma unroll
    for (int u = 0; u < Hd/128; u++) {
        int h = tid + u*128;
        sW[h] = ((const float2*)eoW)[h];
    }
    __syncthreads();
    int m = g_n[b] + 1, mm = m*m;
    float c0 = g_invconst[0], c1 = g_invconst[1];
    for (int ee = 0; ee < 4; ee++) {
        int e = e0 + ee;
        long base = 32 + Bb*Kk*2 + ((long)b*Ee + e)*2;
        if (e >= mm) {
            if (tid == 0) { out[base] = c0; out[base + 1] = c1; }
            continue;
        }
        int i = e / m, j = e - i*m;
        if (i > Kk-1) i = Kk-1;
        if (j > Kk-1) j = Kk-1;
        const float* aj = &g_Aj[(long)(b*Kk + j)*Hd];
        const float* ai = &g_Ai[(long)(b*Kk + i)*Hd];
        float a0 = 0.f, a1 = 0.f;
        #pragma unroll
        for (int u = 0; u < Hd/128; u++) {
            int h = tid + u*128;
            float t = tanh_fast(aj[h] + ai[h]);
            float2 w = sW[h];
            a0 = fmaf(t, w.x, a0);
            a1 = fmaf(t, w.y, a1);
        }
        block_reduce2(a0, a1, red);
        if (tid == 0) { out[base] = a0 + eob[0]; out[base + 1] = a1 + eob[1]; }
        __syncthreads();
    }
}

// ---------------------------------------------------------------------------
extern "C" void kernel_launch(void* const* d_in, const int* in_sizes, int n_in,
                              void* d_out, int out_size) {
    const float* seq   = (const float*)d_in[0];
    const int*   P     = (const int*)d_in[1];
    const float* nafW  = (const float*)d_in[2];
    const float* nafb  = (const float*)d_in[3];
    const float* clsW  = (const float*)d_in[4];
    const float* clsb  = (const float*)d_in[5];
    const float* clsoW = (const float*)d_in[6];
    const float* clsob = (const float*)d_in[7];
    const float* ndW   = (const float*)d_in[8];
    const float* ndb   = (const float*)d_in[9];
    const float* noW   = (const float*)d_in[10];
    const float* nob   = (const float*)d_in[11];
    const float* edW   = (const float*)d_in[12];
    const float* edb   = (const float*)d_in[13];
    const float* eoW   = (const float*)d_in[14];
    const float* eob   = (const float*)d_in[15];
    float* out = (float*)d_out;

    k_meta<<<dim3(Kk, Bb), 256>>>(seq, P);                              // idx 0
    k_wsplit<<<3073, 256>>>(ndW, edW, edb, eoW, eob);                   // idx 1
    k_cls2<<<dim3(Hd/32, 2), 128>>>(seq, nafW, nafb, clsW, clsb);       // idx 2
    k_gemm<<<dim3(NCAT/128, 512/64), 128>>>(ndb, edb);                  // idx 3 (ncu)
    k_post<<<528 + Bb*256, 128>>>(clsoW, clsob, noW, nob, eoW, eob, out); // idx 4
}